// round 4
// baseline (speedup 1.0000x reference)
#include <cuda_runtime.h>
#include <math.h>

#define BB 8
#define NN 512
#define FF 64
#define EE 16
#define HH 4
#define HD 16
#define NPOS (BB*NN*NN)    // 2097152
#define ROWS (BB*NN)       // 4096

// ---------------- scratch ------------------------------------------------------
__device__ float g_h  [ROWS*FF];
__device__ float g_sr [ROWS*HH];
__device__ float g_sc [ROWS*HH];
__device__ float g_se [NPOS];
__device__ float g_msg[ROWS*FF];

// ---------------- packed f32x2 helpers ----------------------------------------
union f2u { float2 f; unsigned long long u; };

__device__ __forceinline__ float2 ffma2(float2 a, float2 b, float2 c) {
    f2u A, Bv, C, D; A.f = a; Bv.f = b; C.f = c;
    asm("fma.rn.f32x2 %0, %1, %2, %3;" : "=l"(D.u) : "l"(A.u), "l"(Bv.u), "l"(C.u));
    return D.f;
}

__device__ __forceinline__ float celu1(float x) {
    return fmaxf(x, 0.f) + __expf(fminf(x, 0.f)) - 1.f;
}

// ---------------- K1: node LN -> Wn GEMM -> sr/sc (32 rows / block) ------------
__global__ __launch_bounds__(256) void k_node(
        const float* __restrict__ node, const float* __restrict__ g1,
        const float* __restrict__ b1, const float* __restrict__ Wn,
        const float* __restrict__ bn, const float* __restrict__ A) {
    __shared__ __align__(16) float ns[32*68];
    __shared__ float Wns[64*65];
    __shared__ __align__(16) float hs[32*68];
    __shared__ float arow[HD], acol[HD];

    int tid = threadIdx.x;
    int row0 = blockIdx.x * 32;

    if (tid < HD) {
        float s = 0.f;
        #pragma unroll
        for (int h = 0; h < HH; h++) s += A[h*48 + tid];
        arow[tid] = s;
    } else if (tid < 2*HD) {
        int x = tid - HD; float s = 0.f;
        #pragma unroll
        for (int h = 0; h < HH; h++) s += A[h*48 + HD + x];
        acol[x] = s;
    }

    {
        const float4* src = (const float4*)(node + (size_t)row0 * FF);
        #pragma unroll
        for (int i = tid; i < 32*16; i += 256) {
            int r = i >> 4, c4 = i & 15;
            *(float4*)&ns[r*68 + c4*4] = src[i];
        }
    }
    #pragma unroll
    for (int i = tid; i < 64*64; i += 256) {
        int f = i >> 6, k = i & 63;
        Wns[f*65 + k] = Wn[i];
    }
    __syncthreads();

    // LN: 8 threads per row
    {
        int r = tid >> 3, sub = tid & 7;
        float s = 0.f;
        #pragma unroll
        for (int t = 0; t < 8; t++) s += ns[r*68 + sub + 8*t];
        s += __shfl_xor_sync(0xffffffffu, s, 1);
        s += __shfl_xor_sync(0xffffffffu, s, 2);
        s += __shfl_xor_sync(0xffffffffu, s, 4);
        float mu = s * (1.f/FF);
        float q = 0.f;
        #pragma unroll
        for (int t = 0; t < 8; t++) { float d = ns[r*68 + sub + 8*t] - mu; q += d*d; }
        q += __shfl_xor_sync(0xffffffffu, q, 1);
        q += __shfl_xor_sync(0xffffffffu, q, 2);
        q += __shfl_xor_sync(0xffffffffu, q, 4);
        float rs = rsqrtf(q * (1.f/FF) + 1e-5f);
        #pragma unroll
        for (int t = 0; t < 8; t++) {
            int k = sub + 8*t;
            ns[r*68 + k] = (ns[r*68 + k] - mu) * rs * g1[k] + b1[k];
        }
    }
    __syncthreads();

    // GEMM: thread = (col f, rowgroup of 8 rows)
    {
        int f  = tid & 63;
        int rg = tid >> 6;
        float acc[8];
        float bv = bn[f];
        #pragma unroll
        for (int t = 0; t < 8; t++) acc[t] = bv;
        #pragma unroll 8
        for (int k = 0; k < 64; k++) {
            float wv = Wns[f*65 + k];
            #pragma unroll
            for (int t = 0; t < 8; t++)
                acc[t] = fmaf(ns[(rg*8 + t)*68 + k], wv, acc[t]);
        }
        #pragma unroll
        for (int t = 0; t < 8; t++) {
            int r = rg*8 + t;
            g_h[(size_t)(row0 + r)*FF + f] = acc[t];
            hs[r*68 + f] = acc[t];
        }
    }
    __syncthreads();

    if (tid < 128) {
        int r = tid >> 2, hh = tid & 3;
        float sr = 0.f, sc = 0.f;
        #pragma unroll
        for (int x = 0; x < HD; x++) {
            float hv = hs[r*68 + hh*HD + x];
            sr = fmaf(hv, arow[x], sr);
            sc = fmaf(hv, acol[x], sc);
        }
        g_sr[(size_t)(row0 + r)*HH + hh] = sr;
        g_sc[(size_t)(row0 + r)*HH + hh] = sc;
    }
}

// ---------------- K2: edge pipeline, register-tiled GEMMs ----------------------
// 128 positions per block, 128 threads.
__global__ __launch_bounds__(128) void k_edge(
    const float* __restrict__ edge,
    const float* __restrict__ g2, const float* __restrict__ b2,
    const float* __restrict__ We1, const float* __restrict__ be1,
    const float* __restrict__ We2, const float* __restrict__ be2,
    const float* __restrict__ lg, const float* __restrict__ lb,
    const float* __restrict__ A, float* __restrict__ e_out) {

    __shared__ __align__(16) float Xs[128*17];     // original edge rows (residual)
    __shared__ __align__(16) float NY[128*17];     // Ns [ch][pos] then Ys [pos][17]
    __shared__ __align__(16) float Hs[32*128];     // hidden [hid][pos]
    __shared__ __align__(16) float W1t[16*32];     // [k][o]
    __shared__ __align__(16) float W2t[32*16];     // [k][o]
    __shared__ float b1s[32], b2s[16], g2s[EE], b2ln[EE], lgs[EE], lbs[EE], aes[EE];

    int tid = threadIdx.x;
    size_t base = (size_t)blockIdx.x * 128;

    // stage weights (transposed) + vectors
    #pragma unroll
    for (int i = tid; i < 512; i += 128) {
        int k = i >> 5, o = i & 31;
        W1t[i] = We1[o*16 + k];
        int k2 = i >> 4, o2 = i & 15;
        W2t[i] = We2[o2*32 + k2];
    }
    if (tid < 32) b1s[tid] = be1[tid];
    if (tid < EE) {
        b2s[tid] = be2[tid];
        g2s[tid] = g2[tid]; b2ln[tid] = b2[tid];
        lgs[tid] = lg[tid]; lbs[tid] = lb[tid];
        float s = 0.f;
        #pragma unroll
        for (int h = 0; h < HH; h++) s += A[h*48 + 2*HD + tid];
        aes[tid] = s;
    }
    // stage edge tile (coalesced float4)
    {
        const float4* src = (const float4*)edge + base*4;
        #pragma unroll
        for (int i = tid; i < 512; i += 128) {
            float4 v = src[i];
            int p = i >> 2, c4 = i & 3;
            float* d = &Xs[p*17 + c4*4];
            d[0] = v.x; d[1] = v.y; d[2] = v.z; d[3] = v.w;
        }
    }
    __syncthreads();

    // phase 1: LN per position -> NY as [ch][pos]
    {
        int p = tid;
        float x[EE];
        float s = 0.f;
        #pragma unroll
        for (int k = 0; k < EE; k++) { x[k] = Xs[p*17 + k]; s += x[k]; }
        float mu = s * (1.f/16.f);
        float q = 0.f;
        #pragma unroll
        for (int k = 0; k < EE; k++) { float d = x[k] - mu; q += d*d; }
        float rs = rsqrtf(q * (1.f/16.f) + 1e-5f);
        #pragma unroll
        for (int k = 0; k < EE; k++)
            NY[k*128 + p] = (x[k] - mu) * rs * g2s[k] + b2ln[k];
    }
    __syncthreads();

    // phase 2: GEMM1 (16 -> 32) + celu, register tile 8 pos x 4 hid
    {
        int pg = tid & 15;        // 16 groups * 8 pos
        int hg = tid >> 4;        // 8 groups * 4 hid
        float2 acc[4][4];
        #pragma unroll
        for (int o = 0; o < 4; o++) {
            float bv = b1s[hg*4 + o];
            #pragma unroll
            for (int j = 0; j < 4; j++) acc[j][o] = make_float2(bv, bv);
        }
        #pragma unroll
        for (int k = 0; k < 16; k++) {
            float4 xa = *(const float4*)&NY[k*128 + pg*8];
            float4 xb = *(const float4*)&NY[k*128 + pg*8 + 4];
            float4 w  = *(const float4*)&W1t[k*32 + hg*4];
            float2 xp[4] = {{xa.x,xa.y},{xa.z,xa.w},{xb.x,xb.y},{xb.z,xb.w}};
            float2 wp[4] = {{w.x,w.x},{w.y,w.y},{w.z,w.z},{w.w,w.w}};
            #pragma unroll
            for (int j = 0; j < 4; j++)
                #pragma unroll
                for (int o = 0; o < 4; o++)
                    acc[j][o] = ffma2(xp[j], wp[o], acc[j][o]);
        }
        #pragma unroll
        for (int o = 0; o < 4; o++) {
            float4 v0 = make_float4(celu1(acc[0][o].x), celu1(acc[0][o].y),
                                    celu1(acc[1][o].x), celu1(acc[1][o].y));
            float4 v1 = make_float4(celu1(acc[2][o].x), celu1(acc[2][o].y),
                                    celu1(acc[3][o].x), celu1(acc[3][o].y));
            *(float4*)&Hs[(hg*4 + o)*128 + pg*8]     = v0;
            *(float4*)&Hs[(hg*4 + o)*128 + pg*8 + 4] = v1;
        }
    }
    __syncthreads();

    // phase 3: GEMM2 (32 -> 16), register tile 8 pos x 2 out, write Ys [pos][17]
    {
        int pg = tid & 15;
        int og = tid >> 4;        // 8 groups * 2 out
        float2 acc[4][2];
        #pragma unroll
        for (int o = 0; o < 2; o++) {
            float bv = b2s[og*2 + o];
            #pragma unroll
            for (int j = 0; j < 4; j++) acc[j][o] = make_float2(bv, bv);
        }
        #pragma unroll
        for (int k = 0; k < 32; k++) {
            float4 ha = *(const float4*)&Hs[k*128 + pg*8];
            float4 hb = *(const float4*)&Hs[k*128 + pg*8 + 4];
            float2 w  = *(const float2*)&W2t[k*16 + og*2];
            float2 hp[4] = {{ha.x,ha.y},{ha.z,ha.w},{hb.x,hb.y},{hb.z,hb.w}};
            float2 w0 = make_float2(w.x, w.x), w1 = make_float2(w.y, w.y);
            #pragma unroll
            for (int j = 0; j < 4; j++) {
                acc[j][0] = ffma2(hp[j], w0, acc[j][0]);
                acc[j][1] = ffma2(hp[j], w1, acc[j][1]);
            }
        }
        __syncthreads();   // NY (Ns) fully consumed by phase-2 readers before overwrite
        #pragma unroll
        for (int j = 0; j < 4; j++) {
            int p0 = pg*8 + 2*j, p1 = p0 + 1;
            #pragma unroll
            for (int o = 0; o < 2; o++) {
                NY[p0*17 + og*2 + o] = acc[j][o].x;
                NY[p1*17 + og*2 + o] = acc[j][o].y;
            }
        }
    }
    __syncthreads();

    // phase 4: residual + final LN + se per position
    {
        int p = tid;
        float y[EE];
        float s = 0.f;
        #pragma unroll
        for (int k = 0; k < EE; k++) {
            y[k] = NY[p*17 + k] + Xs[p*17 + k];
            s += y[k];
        }
        float mu = s * (1.f/16.f);
        float q = 0.f;
        #pragma unroll
        for (int k = 0; k < EE; k++) { float d = y[k] - mu; q += d*d; }
        float rs = rsqrtf(q * (1.f/16.f) + 1e-5f);
        float se = 0.f;
        #pragma unroll
        for (int k = 0; k < EE; k++) {
            float yv = (y[k] - mu) * rs * lgs[k] + lbs[k];
            NY[p*17 + k] = yv;
            se = fmaf(yv, aes[k], se);
        }
        g_se[base + p] = se;
    }
    __syncthreads();

    // phase 5: coalesced store of e
    {
        float4* dst = (float4*)e_out + base*4;
        #pragma unroll
        for (int i = tid; i < 512; i += 128) {
            int p = i >> 2, c4 = i & 3;
            const float* sp = &NY[p*17 + c4*4];
            dst[i] = make_float4(sp[0], sp[1], sp[2], sp[3]);
        }
    }
}

// ---------------- K3: two-pass masked leaky softmax + aggregation --------------
__global__ __launch_bounds__(256) void k_attn(const int* __restrict__ adj) {
    __shared__ __align__(16) float hsm[128*64];
    __shared__ float scs[128*4];

    int tid = threadIdx.x;
    int sub = tid & 3;
    int hh  = (tid >> 2) & 3;
    int il  = tid >> 4;
    int b = blockIdx.y;
    int ig = blockIdx.x * 16 + il;
    int rowi = b*NN + ig;

    const float* sep = g_se + (size_t)rowi * NN;
    const int*   ap  = adj  + (size_t)rowi * NN;
    float sr_v = g_sr[rowi*HH + hh];
    const float* scg = g_sc + (size_t)b*NN*HH;

    float m = -3.4e38f;
    #pragma unroll 4
    for (int t = 0; t < 128; t++) {
        int j = sub + 4*t;
        float lgt = sr_v + scg[j*HH + hh] + sep[j];
        if (ap[j] == 0) lgt = -1e9f;
        lgt = lgt > 0.f ? lgt : 0.2f*lgt;
        lgt = fminf(fmaxf(lgt, -1e9f), 1e9f);
        m = fmaxf(m, lgt);
    }
    m = fmaxf(m, __shfl_xor_sync(0xffffffffu, m, 1));
    m = fmaxf(m, __shfl_xor_sync(0xffffffffu, m, 2));

    float ssum = 0.f;
    float a0 = 0.f, a1 = 0.f, a2 = 0.f, a3 = 0.f;
    for (int jt = 0; jt < 4; jt++) {
        int j0 = jt * 128;
        __syncthreads();
        {
            const float4* hsrc = (const float4*)(g_h + (size_t)(b*NN + j0) * FF);
            #pragma unroll
            for (int i = tid; i < 128*16; i += 256) ((float4*)hsm)[i] = hsrc[i];
            if (tid < 128)
                ((float4*)scs)[tid] = ((const float4*)(scg + (size_t)j0*HH))[tid];
        }
        __syncthreads();
        #pragma unroll 2
        for (int jl = 0; jl < 128; jl++) {
            int j = j0 + jl;
            float lgt = sr_v + scs[jl*4 + hh] + sep[j];
            if (ap[j] == 0) lgt = -1e9f;
            lgt = lgt > 0.f ? lgt : 0.2f*lgt;
            lgt = fminf(fmaxf(lgt, -1e9f), 1e9f);
            float w = __expf(lgt - m);
            ssum += w;
            float4 hv = *(const float4*)(hsm + jl*64 + hh*16 + sub*4);
            a0 = fmaf(w, hv.x, a0);
            a1 = fmaf(w, hv.y, a1);
            a2 = fmaf(w, hv.z, a2);
            a3 = fmaf(w, hv.w, a3);
        }
    }
    float inv = 1.f / ssum;
    *(float4*)(g_msg + (size_t)rowi*FF + hh*16 + sub*4) =
        make_float4(a0*inv, a1*inv, a2*inv, a3*inv);
}

// ---------------- K4: out proj + residual + leaky + LN (32 rows / block) -------
__global__ __launch_bounds__(256) void k_out(
        const float* __restrict__ node, const float* __restrict__ Wo,
        const float* __restrict__ bo, const float* __restrict__ lg,
        const float* __restrict__ lb, float* __restrict__ outp) {
    __shared__ __align__(16) float ms[32*68];
    __shared__ float Wos[64*65];
    __shared__ __align__(16) float hsr[32*68];

    int tid = threadIdx.x;
    int row0 = blockIdx.x * 32;

    {
        const float4* src = (const float4*)(g_msg + (size_t)row0 * FF);
        #pragma unroll
        for (int i = tid; i < 32*16; i += 256) {
            int r = i >> 4, c4 = i & 15;
            *(float4*)&ms[r*68 + c4*4] = src[i];
        }
    }
    #pragma unroll
    for (int i = tid; i < 64*64; i += 256) {
        int f = i >> 6, k = i & 63;
        Wos[f*65 + k] = Wo[i];
    }
    __syncthreads();

    {
        int f  = tid & 63;
        int rg = tid >> 6;
        float acc[8];
        float bv = bo[f];
        #pragma unroll
        for (int t = 0; t < 8; t++) acc[t] = bv;
        #pragma unroll 8
        for (int k = 0; k < 64; k++) {
            float wv = Wos[f*65 + k];
            #pragma unroll
            for (int t = 0; t < 8; t++)
                acc[t] = fmaf(ms[(rg*8 + t)*68 + k], wv, acc[t]);
        }
        #pragma unroll
        for (int t = 0; t < 8; t++) {
            int r = rg*8 + t;
            float v = acc[t] + node[(size_t)(row0 + r)*FF + f];
            v = v > 0.f ? v : 0.2f*v;
            hsr[r*68 + f] = v;
        }
    }
    __syncthreads();

    {
        int r = tid >> 3, sub = tid & 7;
        float s = 0.f;
        #pragma unroll
        for (int t = 0; t < 8; t++) s += hsr[r*68 + sub + 8*t];
        s += __shfl_xor_sync(0xffffffffu, s, 1);
        s += __shfl_xor_sync(0xffffffffu, s, 2);
        s += __shfl_xor_sync(0xffffffffu, s, 4);
        float mu = s * (1.f/FF);
        float q = 0.f;
        #pragma unroll
        for (int t = 0; t < 8; t++) { float d = hsr[r*68 + sub + 8*t] - mu; q += d*d; }
        q += __shfl_xor_sync(0xffffffffu, q, 1);
        q += __shfl_xor_sync(0xffffffffu, q, 2);
        q += __shfl_xor_sync(0xffffffffu, q, 4);
        float rsv = rsqrtf(q * (1.f/FF) + 1e-5f);
        #pragma unroll
        for (int t = 0; t < 8; t++) {
            int k = sub + 8*t;
            outp[(size_t)(row0 + r)*FF + k] = (hsr[r*68 + k] - mu) * rsv * lg[k] + lb[k];
        }
    }
}

// ---------------- K5: adj -> float copy ---------------------------------------
__global__ void k_adj(const int* __restrict__ adj, float* __restrict__ oadj) {
    int i = blockIdx.x * 256 + threadIdx.x;
    const int4* s = (const int4*)adj;
    float4* d = (float4*)oadj;
    int4 v = s[i];
    d[i] = make_float4((float)v.x, (float)v.y, (float)v.z, (float)v.w);
}

// ---------------- launch -------------------------------------------------------
extern "C" void kernel_launch(void* const* d_in, const int* in_sizes, int n_in,
                              void* d_out, int out_size) {
    const float* node  = (const float*)d_in[0];
    const float* edge  = (const float*)d_in[1];
    const int*   adj   = (const int*)  d_in[2];
    const float* ln1_g = (const float*)d_in[3];
    const float* ln1_b = (const float*)d_in[4];
    const float* Wn    = (const float*)d_in[5];
    const float* bn    = (const float*)d_in[6];
    const float* ln2_g = (const float*)d_in[7];
    const float* ln2_b = (const float*)d_in[8];
    const float* We1   = (const float*)d_in[9];
    const float* be1   = (const float*)d_in[10];
    const float* We2   = (const float*)d_in[11];
    const float* be2   = (const float*)d_in[12];
    const float* lne_g = (const float*)d_in[13];
    const float* lne_b = (const float*)d_in[14];
    const float* attnA = (const float*)d_in[15];
    const float* Wo    = (const float*)d_in[16];
    const float* bo    = (const float*)d_in[17];
    const float* lno_g = (const float*)d_in[18];
    const float* lno_b = (const float*)d_in[19];

    float* out     = (float*)d_out;
    float* e_out   = out + (size_t)ROWS * FF;
    float* adj_out = e_out + (size_t)NPOS * EE;

    k_node<<<ROWS/32, 256>>>(node, ln1_g, ln1_b, Wn, bn, attnA);
    k_edge<<<NPOS/128, 128>>>(edge, ln2_g, ln2_b, We1, be1, We2, be2,
                              lne_g, lne_b, attnA, e_out);
    k_attn<<<dim3(NN/16, BB), 256>>>(adj);
    k_out<<<ROWS/32, 256>>>(node, Wo, bo, lno_g, lno_b, out);
    k_adj<<<NPOS/1024, 256>>>(adj, adj_out);
}

// round 5
// speedup vs baseline: 1.6139x; 1.6139x over previous
#include <cuda_runtime.h>
#include <math.h>

#define BB 8
#define NN 512
#define FF 64
#define EE 16
#define HH 4
#define HD 16
#define NPOS (BB*NN*NN)    // 2097152
#define ROWS (BB*NN)       // 4096

// ---------------- scratch ------------------------------------------------------
__device__ float g_h  [ROWS*FF];
__device__ float g_sr [ROWS*HH];
__device__ float g_sc [ROWS*HH];
__device__ float g_se [NPOS];
__device__ float g_msg[ROWS*FF];

// ---------------- packed f32x2 helpers ----------------------------------------
union f2u { float2 f; unsigned long long u; };

__device__ __forceinline__ float2 ffma2(float2 a, float2 b, float2 c) {
    f2u A, Bv, C, D; A.f = a; Bv.f = b; C.f = c;
    asm("fma.rn.f32x2 %0, %1, %2, %3;" : "=l"(D.u) : "l"(A.u), "l"(Bv.u), "l"(C.u));
    return D.f;
}
__device__ __forceinline__ float2 fadd2(float2 a, float2 b) {
    f2u A, Bv, D; A.f = a; Bv.f = b;
    asm("add.rn.f32x2 %0, %1, %2;" : "=l"(D.u) : "l"(A.u), "l"(Bv.u));
    return D.f;
}
__device__ __forceinline__ float2 fmul2(float2 a, float2 b) {
    f2u A, Bv, D; A.f = a; Bv.f = b;
    asm("mul.rn.f32x2 %0, %1, %2;" : "=l"(D.u) : "l"(A.u), "l"(Bv.u));
    return D.f;
}
__device__ __forceinline__ float celu1(float x) {
    return fmaxf(x, 0.f) + __expf(fminf(x, 0.f)) - 1.f;
}

// ---------------- K1: node LN -> Wn GEMM -> sr/sc (32 rows / block) ------------
__global__ __launch_bounds__(256) void k_node(
        const float* __restrict__ node, const float* __restrict__ g1,
        const float* __restrict__ b1, const float* __restrict__ Wn,
        const float* __restrict__ bn, const float* __restrict__ A) {
    __shared__ __align__(16) float ns[32*68];
    __shared__ float Wns[64*65];
    __shared__ __align__(16) float hs[32*68];
    __shared__ float arow[HD], acol[HD];

    int tid = threadIdx.x;
    int row0 = blockIdx.x * 32;

    if (tid < HD) {
        float s = 0.f;
        #pragma unroll
        for (int h = 0; h < HH; h++) s += A[h*48 + tid];
        arow[tid] = s;
    } else if (tid < 2*HD) {
        int x = tid - HD; float s = 0.f;
        #pragma unroll
        for (int h = 0; h < HH; h++) s += A[h*48 + HD + x];
        acol[x] = s;
    }

    {
        const float4* src = (const float4*)(node + (size_t)row0 * FF);
        #pragma unroll
        for (int i = tid; i < 32*16; i += 256) {
            int r = i >> 4, c4 = i & 15;
            *(float4*)&ns[r*68 + c4*4] = src[i];
        }
    }
    #pragma unroll
    for (int i = tid; i < 64*64; i += 256) {
        int f = i >> 6, k = i & 63;
        Wns[f*65 + k] = Wn[i];
    }
    __syncthreads();

    {
        int r = tid >> 3, sub = tid & 7;
        float s = 0.f;
        #pragma unroll
        for (int t = 0; t < 8; t++) s += ns[r*68 + sub + 8*t];
        s += __shfl_xor_sync(0xffffffffu, s, 1);
        s += __shfl_xor_sync(0xffffffffu, s, 2);
        s += __shfl_xor_sync(0xffffffffu, s, 4);
        float mu = s * (1.f/FF);
        float q = 0.f;
        #pragma unroll
        for (int t = 0; t < 8; t++) { float d = ns[r*68 + sub + 8*t] - mu; q += d*d; }
        q += __shfl_xor_sync(0xffffffffu, q, 1);
        q += __shfl_xor_sync(0xffffffffu, q, 2);
        q += __shfl_xor_sync(0xffffffffu, q, 4);
        float rs = rsqrtf(q * (1.f/FF) + 1e-5f);
        #pragma unroll
        for (int t = 0; t < 8; t++) {
            int k = sub + 8*t;
            ns[r*68 + k] = (ns[r*68 + k] - mu) * rs * g1[k] + b1[k];
        }
    }
    __syncthreads();

    {
        int f  = tid & 63;
        int rg = tid >> 6;
        float acc[8];
        float bv = bn[f];
        #pragma unroll
        for (int t = 0; t < 8; t++) acc[t] = bv;
        #pragma unroll 8
        for (int k = 0; k < 64; k++) {
            float wv = Wns[f*65 + k];
            #pragma unroll
            for (int t = 0; t < 8; t++)
                acc[t] = fmaf(ns[(rg*8 + t)*68 + k], wv, acc[t]);
        }
        #pragma unroll
        for (int t = 0; t < 8; t++) {
            int r = rg*8 + t;
            g_h[(size_t)(row0 + r)*FF + f] = acc[t];
            hs[r*68 + f] = acc[t];
        }
    }
    __syncthreads();

    if (tid < 128) {
        int r = tid >> 2, hh = tid & 3;
        float sr = 0.f, sc = 0.f;
        #pragma unroll
        for (int x = 0; x < HD; x++) {
            float hv = hs[r*68 + hh*HD + x];
            sr = fmaf(hv, arow[x], sr);
            sc = fmaf(hv, acol[x], sc);
        }
        g_sr[(size_t)(row0 + r)*HH + hh] = sr;
        g_sc[(size_t)(row0 + r)*HH + hh] = sc;
    }
}

// ---------------- K2: edge pipeline, 4 positions/thread, no staging ------------
// 128 threads, 512 positions per block. Thread t owns positions t, t+128, t+256, t+384.
// f32x2 lane pairs: (t, t+128) and (t+256, t+384).
__global__ __launch_bounds__(128, 2) void k_edge(
    const float* __restrict__ edge, const int* __restrict__ adj,
    const float* __restrict__ g2, const float* __restrict__ b2,
    const float* __restrict__ We1, const float* __restrict__ be1,
    const float* __restrict__ We2, const float* __restrict__ be2,
    const float* __restrict__ lg, const float* __restrict__ lb,
    const float* __restrict__ A,
    float* __restrict__ e_out, float* __restrict__ adj_out) {

    __shared__ float2 W1s[32*16], W2s[16*32];
    __shared__ float2 ln2g[EE], ln2b[EE], lneg[EE], lneb[EE], be1s[32], be2s[EE], aes[EE];

    int tid = threadIdx.x;
    for (int i = tid; i < 512; i += 128) {
        float w = We1[i]; W1s[i] = make_float2(w, w);
        float w2 = We2[i]; W2s[i] = make_float2(w2, w2);
    }
    if (tid < EE) {
        ln2g[tid] = make_float2(g2[tid], g2[tid]);
        ln2b[tid] = make_float2(b2[tid], b2[tid]);
        lneg[tid] = make_float2(lg[tid], lg[tid]);
        lneb[tid] = make_float2(lb[tid], lb[tid]);
        be2s[tid] = make_float2(be2[tid], be2[tid]);
        float s = 0.f;
        #pragma unroll
        for (int h = 0; h < HH; h++) s += A[h*48 + 2*HD + tid];
        aes[tid] = make_float2(s, s);
    }
    if (tid < 32) be1s[tid] = make_float2(be1[tid], be1[tid]);

    // adj -> float (coalesced, independent of weights)
    size_t base = (size_t)blockIdx.x * 512;
    {
        int4 av = ((const int4*)(adj + base))[tid];
        ((float4*)(adj_out + base))[tid] =
            make_float4((float)av.x, (float)av.y, (float)av.z, (float)av.w);
    }
    __syncthreads();

    const float4* e4 = (const float4*)edge;
    const float2 zero2 = make_float2(0.f, 0.f);
    const float2 neg1  = make_float2(-1.f, -1.f);
    const float2 inv16 = make_float2(1.f/16.f, 1.f/16.f);

    size_t pA = base + tid, pB = base + tid + 128;
    size_t pC = base + tid + 256, pD = base + tid + 384;

    float2 X0[EE], X1[EE];
    {
        float fa[EE], fb[EE], fc[EE], fd[EE];
        #pragma unroll
        for (int i = 0; i < 4; i++) {
            *(float4*)&fa[i*4] = e4[pA*4 + i];
            *(float4*)&fb[i*4] = e4[pB*4 + i];
            *(float4*)&fc[i*4] = e4[pC*4 + i];
            *(float4*)&fd[i*4] = e4[pD*4 + i];
        }
        #pragma unroll
        for (int k = 0; k < EE; k++) {
            X0[k] = make_float2(fa[k], fb[k]);
            X1[k] = make_float2(fc[k], fd[k]);
        }
    }

    // LN over E (both lane-pairs)
    {
        float2 s0 = zero2, s1 = zero2;
        #pragma unroll
        for (int k = 0; k < EE; k++) { s0 = fadd2(s0, X0[k]); s1 = fadd2(s1, X1[k]); }
        float2 mu0 = fmul2(s0, inv16), mu1 = fmul2(s1, inv16);
        float2 q0 = zero2, q1 = zero2;
        #pragma unroll
        for (int k = 0; k < EE; k++) {
            float2 d0 = ffma2(mu0, neg1, X0[k]); q0 = ffma2(d0, d0, q0);
            float2 d1 = ffma2(mu1, neg1, X1[k]); q1 = ffma2(d1, d1, q1);
        }
        float2 v0 = fmul2(q0, inv16), v1 = fmul2(q1, inv16);
        float2 rs0 = make_float2(rsqrtf(v0.x + 1e-5f), rsqrtf(v0.y + 1e-5f));
        float2 rs1 = make_float2(rsqrtf(v1.x + 1e-5f), rsqrtf(v1.y + 1e-5f));
        #pragma unroll
        for (int k = 0; k < EE; k++) {
            float2 d0 = ffma2(mu0, neg1, X0[k]);
            float2 d1 = ffma2(mu1, neg1, X1[k]);
            X0[k] = ffma2(d0, fmul2(rs0, ln2g[k]), ln2b[k]);
            X1[k] = ffma2(d1, fmul2(rs1, ln2g[k]), ln2b[k]);
        }
    }

    // fused GEMM1 -> celu -> GEMM2 (weights read once per thread, 4 positions)
    float2 Y0[EE], Y1[EE];
    #pragma unroll
    for (int o = 0; o < EE; o++) { Y0[o] = be2s[o]; Y1[o] = be2s[o]; }
    #pragma unroll 2
    for (int kk = 0; kk < 32; kk++) {
        float2 a0 = be1s[kk], a1 = a0;
        #pragma unroll
        for (int k = 0; k < 16; k++) {
            float2 w = W1s[kk*16 + k];
            a0 = ffma2(X0[k], w, a0);
            a1 = ffma2(X1[k], w, a1);
        }
        float2 hc0 = make_float2(celu1(a0.x), celu1(a0.y));
        float2 hc1 = make_float2(celu1(a1.x), celu1(a1.y));
        #pragma unroll
        for (int o = 0; o < 16; o++) {
            float2 w = W2s[o*32 + kk];
            Y0[o] = ffma2(hc0, w, Y0[o]);
            Y1[o] = ffma2(hc1, w, Y1[o]);
        }
    }

    // residual (edge reload: L1-hot)
    {
        float fa[EE], fb[EE], fc[EE], fd[EE];
        #pragma unroll
        for (int i = 0; i < 4; i++) {
            *(float4*)&fa[i*4] = e4[pA*4 + i];
            *(float4*)&fb[i*4] = e4[pB*4 + i];
            *(float4*)&fc[i*4] = e4[pC*4 + i];
            *(float4*)&fd[i*4] = e4[pD*4 + i];
        }
        #pragma unroll
        for (int k = 0; k < EE; k++) {
            Y0[k] = fadd2(Y0[k], make_float2(fa[k], fb[k]));
            Y1[k] = fadd2(Y1[k], make_float2(fc[k], fd[k]));
        }
    }

    // final LN + se
    {
        float2 s0 = zero2, s1 = zero2;
        #pragma unroll
        for (int k = 0; k < EE; k++) { s0 = fadd2(s0, Y0[k]); s1 = fadd2(s1, Y1[k]); }
        float2 mu0 = fmul2(s0, inv16), mu1 = fmul2(s1, inv16);
        float2 q0 = zero2, q1 = zero2;
        #pragma unroll
        for (int k = 0; k < EE; k++) {
            float2 d0 = ffma2(mu0, neg1, Y0[k]); q0 = ffma2(d0, d0, q0);
            float2 d1 = ffma2(mu1, neg1, Y1[k]); q1 = ffma2(d1, d1, q1);
        }
        float2 v0 = fmul2(q0, inv16), v1 = fmul2(q1, inv16);
        float2 rs0 = make_float2(rsqrtf(v0.x + 1e-5f), rsqrtf(v0.y + 1e-5f));
        float2 rs1 = make_float2(rsqrtf(v1.x + 1e-5f), rsqrtf(v1.y + 1e-5f));
        float2 se0 = zero2, se1 = zero2;
        #pragma unroll
        for (int k = 0; k < EE; k++) {
            float2 d0 = ffma2(mu0, neg1, Y0[k]);
            float2 d1 = ffma2(mu1, neg1, Y1[k]);
            Y0[k] = ffma2(d0, fmul2(rs0, lneg[k]), lneb[k]);
            Y1[k] = ffma2(d1, fmul2(rs1, lneg[k]), lneb[k]);
            se0 = ffma2(Y0[k], aes[k], se0);
            se1 = ffma2(Y1[k], aes[k], se1);
        }
        g_se[pA] = se0.x; g_se[pB] = se0.y;
        g_se[pC] = se1.x; g_se[pD] = se1.y;
    }

    // stores (float4 per position)
    {
        float4* eo = (float4*)e_out;
        #pragma unroll
        for (int i = 0; i < 4; i++) {
            eo[pA*4 + i] = make_float4(Y0[i*4+0].x, Y0[i*4+1].x, Y0[i*4+2].x, Y0[i*4+3].x);
            eo[pB*4 + i] = make_float4(Y0[i*4+0].y, Y0[i*4+1].y, Y0[i*4+2].y, Y0[i*4+3].y);
            eo[pC*4 + i] = make_float4(Y1[i*4+0].x, Y1[i*4+1].x, Y1[i*4+2].x, Y1[i*4+3].x);
            eo[pD*4 + i] = make_float4(Y1[i*4+0].y, Y1[i*4+1].y, Y1[i*4+2].y, Y1[i*4+3].y);
        }
    }
}

// ---------------- K3: two-pass masked leaky softmax + aggregation --------------
__global__ __launch_bounds__(256) void k_attn(const int* __restrict__ adj) {
    __shared__ __align__(16) float hsm[128*64];
    __shared__ float scs[128*4];

    int tid = threadIdx.x;
    int sub = tid & 3;
    int hh  = (tid >> 2) & 3;
    int il  = tid >> 4;
    int b = blockIdx.y;
    int ig = blockIdx.x * 16 + il;
    int rowi = b*NN + ig;

    const float* sep = g_se + (size_t)rowi * NN;
    const int*   ap  = adj  + (size_t)rowi * NN;
    float sr_v = g_sr[rowi*HH + hh];
    const float* scg = g_sc + (size_t)b*NN*HH;

    float m = -3.4e38f;
    #pragma unroll 4
    for (int t = 0; t < 128; t++) {
        int j = sub + 4*t;
        float lgt = sr_v + scg[j*HH + hh] + sep[j];
        if (ap[j] == 0) lgt = -1e9f;
        lgt = lgt > 0.f ? lgt : 0.2f*lgt;
        lgt = fminf(fmaxf(lgt, -1e9f), 1e9f);
        m = fmaxf(m, lgt);
    }
    m = fmaxf(m, __shfl_xor_sync(0xffffffffu, m, 1));
    m = fmaxf(m, __shfl_xor_sync(0xffffffffu, m, 2));

    float ssum = 0.f;
    float a0 = 0.f, a1 = 0.f, a2 = 0.f, a3 = 0.f;
    for (int jt = 0; jt < 4; jt++) {
        int j0 = jt * 128;
        __syncthreads();
        {
            const float4* hsrc = (const float4*)(g_h + (size_t)(b*NN + j0) * FF);
            #pragma unroll
            for (int i = tid; i < 128*16; i += 256) ((float4*)hsm)[i] = hsrc[i];
            if (tid < 128)
                ((float4*)scs)[tid] = ((const float4*)(scg + (size_t)j0*HH))[tid];
        }
        __syncthreads();
        #pragma unroll 2
        for (int jl = 0; jl < 128; jl++) {
            int j = j0 + jl;
            float lgt = sr_v + scs[jl*4 + hh] + sep[j];
            if (ap[j] == 0) lgt = -1e9f;
            lgt = lgt > 0.f ? lgt : 0.2f*lgt;
            lgt = fminf(fmaxf(lgt, -1e9f), 1e9f);
            float w = __expf(lgt - m);
            ssum += w;
            float4 hv = *(const float4*)(hsm + jl*64 + hh*16 + sub*4);
            a0 = fmaf(w, hv.x, a0);
            a1 = fmaf(w, hv.y, a1);
            a2 = fmaf(w, hv.z, a2);
            a3 = fmaf(w, hv.w, a3);
        }
    }
    float inv = 1.f / ssum;
    *(float4*)(g_msg + (size_t)rowi*FF + hh*16 + sub*4) =
        make_float4(a0*inv, a1*inv, a2*inv, a3*inv);
}

// ---------------- K4: out proj + residual + leaky + LN (32 rows / block) -------
__global__ __launch_bounds__(256) void k_out(
        const float* __restrict__ node, const float* __restrict__ Wo,
        const float* __restrict__ bo, const float* __restrict__ lg,
        const float* __restrict__ lb, float* __restrict__ outp) {
    __shared__ __align__(16) float ms[32*68];
    __shared__ float Wos[64*65];
    __shared__ __align__(16) float hsr[32*68];

    int tid = threadIdx.x;
    int row0 = blockIdx.x * 32;

    {
        const float4* src = (const float4*)(g_msg + (size_t)row0 * FF);
        #pragma unroll
        for (int i = tid; i < 32*16; i += 256) {
            int r = i >> 4, c4 = i & 15;
            *(float4*)&ms[r*68 + c4*4] = src[i];
        }
    }
    #pragma unroll
    for (int i = tid; i < 64*64; i += 256) {
        int f = i >> 6, k = i & 63;
        Wos[f*65 + k] = Wo[i];
    }
    __syncthreads();

    {
        int f  = tid & 63;
        int rg = tid >> 6;
        float acc[8];
        float bv = bo[f];
        #pragma unroll
        for (int t = 0; t < 8; t++) acc[t] = bv;
        #pragma unroll 8
        for (int k = 0; k < 64; k++) {
            float wv = Wos[f*65 + k];
            #pragma unroll
            for (int t = 0; t < 8; t++)
                acc[t] = fmaf(ms[(rg*8 + t)*68 + k], wv, acc[t]);
        }
        #pragma unroll
        for (int t = 0; t < 8; t++) {
            int r = rg*8 + t;
            float v = acc[t] + node[(size_t)(row0 + r)*FF + f];
            v = v > 0.f ? v : 0.2f*v;
            hsr[r*68 + f] = v;
        }
    }
    __syncthreads();

    {
        int r = tid >> 3, sub = tid & 7;
        float s = 0.f;
        #pragma unroll
        for (int t = 0; t < 8; t++) s += hsr[r*68 + sub + 8*t];
        s += __shfl_xor_sync(0xffffffffu, s, 1);
        s += __shfl_xor_sync(0xffffffffu, s, 2);
        s += __shfl_xor_sync(0xffffffffu, s, 4);
        float mu = s * (1.f/FF);
        float q = 0.f;
        #pragma unroll
        for (int t = 0; t < 8; t++) { float d = hsr[r*68 + sub + 8*t] - mu; q += d*d; }
        q += __shfl_xor_sync(0xffffffffu, q, 1);
        q += __shfl_xor_sync(0xffffffffu, q, 2);
        q += __shfl_xor_sync(0xffffffffu, q, 4);
        float rsv = rsqrtf(q * (1.f/FF) + 1e-5f);
        #pragma unroll
        for (int t = 0; t < 8; t++) {
            int k = sub + 8*t;
            outp[(size_t)(row0 + r)*FF + k] = (hsr[r*68 + k] - mu) * rsv * lg[k] + lb[k];
        }
    }
}

// ---------------- launch -------------------------------------------------------
extern "C" void kernel_launch(void* const* d_in, const int* in_sizes, int n_in,
                              void* d_out, int out_size) {
    const float* node  = (const float*)d_in[0];
    const float* edge  = (const float*)d_in[1];
    const int*   adj   = (const int*)  d_in[2];
    const float* ln1_g = (const float*)d_in[3];
    const float* ln1_b = (const float*)d_in[4];
    const float* Wn    = (const float*)d_in[5];
    const float* bn    = (const float*)d_in[6];
    const float* ln2_g = (const float*)d_in[7];
    const float* ln2_b = (const float*)d_in[8];
    const float* We1   = (const float*)d_in[9];
    const float* be1   = (const float*)d_in[10];
    const float* We2   = (const float*)d_in[11];
    const float* be2   = (const float*)d_in[12];
    const float* lne_g = (const float*)d_in[13];
    const float* lne_b = (const float*)d_in[14];
    const float* attnA = (const float*)d_in[15];
    const float* Wo    = (const float*)d_in[16];
    const float* bo    = (const float*)d_in[17];
    const float* lno_g = (const float*)d_in[18];
    const float* lno_b = (const float*)d_in[19];

    float* out     = (float*)d_out;
    float* e_out   = out + (size_t)ROWS * FF;
    float* adj_out = e_out + (size_t)NPOS * EE;

    k_node<<<ROWS/32, 256>>>(node, ln1_g, ln1_b, Wn, bn, attnA);
    k_edge<<<NPOS/512, 128>>>(edge, adj, ln2_g, ln2_b, We1, be1, We2, be2,
                              lne_g, lne_b, attnA, e_out, adj_out);
    k_attn<<<dim3(NN/16, BB), 256>>>(adj);
    k_out<<<ROWS/32, 256>>>(node, Wo, bo, lno_g, lno_b, out);
}

// round 6
// speedup vs baseline: 1.6282x; 1.0089x over previous
#include <cuda_runtime.h>
#include <math.h>

#define BB 8
#define NN 512
#define FF 64
#define EE 16
#define HH 4
#define HD 16
#define NPOS (BB*NN*NN)    // 2097152
#define ROWS (BB*NN)       // 4096

// ---------------- scratch ------------------------------------------------------
__device__ float g_h  [ROWS*FF];
__device__ float g_sr [ROWS*HH];
__device__ float g_sc [ROWS*HH];
__device__ float g_se [NPOS];
__device__ float g_msg[ROWS*FF];

// ---------------- packed f32x2 helpers ----------------------------------------
union f2u { float2 f; unsigned long long u; };

__device__ __forceinline__ float2 ffma2(float2 a, float2 b, float2 c) {
    f2u A, Bv, C, D; A.f = a; Bv.f = b; C.f = c;
    asm("fma.rn.f32x2 %0, %1, %2, %3;" : "=l"(D.u) : "l"(A.u), "l"(Bv.u), "l"(C.u));
    return D.f;
}
__device__ __forceinline__ float2 fadd2(float2 a, float2 b) {
    f2u A, Bv, D; A.f = a; Bv.f = b;
    asm("add.rn.f32x2 %0, %1, %2;" : "=l"(D.u) : "l"(A.u), "l"(Bv.u));
    return D.f;
}
__device__ __forceinline__ float2 fmul2(float2 a, float2 b) {
    f2u A, Bv, D; A.f = a; Bv.f = b;
    asm("mul.rn.f32x2 %0, %1, %2;" : "=l"(D.u) : "l"(A.u), "l"(Bv.u));
    return D.f;
}
__device__ __forceinline__ float2 celu2(float2 a) {
    return make_float2(fmaxf(a.x, 0.f) + __expf(fminf(a.x, 0.f)) - 1.f,
                       fmaxf(a.y, 0.f) + __expf(fminf(a.y, 0.f)) - 1.f);
}

// ---------------- K1: node LN -> Wn GEMM -> sr/sc (32 rows / block) ------------
__global__ __launch_bounds__(256) void k_node(
        const float* __restrict__ node, const float* __restrict__ g1,
        const float* __restrict__ b1, const float* __restrict__ Wn,
        const float* __restrict__ bn, const float* __restrict__ A) {
    __shared__ __align__(16) float ns[32*68];
    __shared__ float Wns[64*65];
    __shared__ __align__(16) float hs[32*68];
    __shared__ float arow[HD], acol[HD];

    int tid = threadIdx.x;
    int row0 = blockIdx.x * 32;

    if (tid < HD) {
        float s = 0.f;
        #pragma unroll
        for (int h = 0; h < HH; h++) s += A[h*48 + tid];
        arow[tid] = s;
    } else if (tid < 2*HD) {
        int x = tid - HD; float s = 0.f;
        #pragma unroll
        for (int h = 0; h < HH; h++) s += A[h*48 + HD + x];
        acol[x] = s;
    }

    {
        const float4* src = (const float4*)(node + (size_t)row0 * FF);
        #pragma unroll
        for (int i = tid; i < 32*16; i += 256) {
            int r = i >> 4, c4 = i & 15;
            *(float4*)&ns[r*68 + c4*4] = src[i];
        }
    }
    #pragma unroll
    for (int i = tid; i < 64*64; i += 256) {
        int f = i >> 6, k = i & 63;
        Wns[f*65 + k] = Wn[i];
    }
    __syncthreads();

    {
        int r = tid >> 3, sub = tid & 7;
        float s = 0.f;
        #pragma unroll
        for (int t = 0; t < 8; t++) s += ns[r*68 + sub + 8*t];
        s += __shfl_xor_sync(0xffffffffu, s, 1);
        s += __shfl_xor_sync(0xffffffffu, s, 2);
        s += __shfl_xor_sync(0xffffffffu, s, 4);
        float mu = s * (1.f/FF);
        float q = 0.f;
        #pragma unroll
        for (int t = 0; t < 8; t++) { float d = ns[r*68 + sub + 8*t] - mu; q += d*d; }
        q += __shfl_xor_sync(0xffffffffu, q, 1);
        q += __shfl_xor_sync(0xffffffffu, q, 2);
        q += __shfl_xor_sync(0xffffffffu, q, 4);
        float rs = rsqrtf(q * (1.f/FF) + 1e-5f);
        #pragma unroll
        for (int t = 0; t < 8; t++) {
            int k = sub + 8*t;
            ns[r*68 + k] = (ns[r*68 + k] - mu) * rs * g1[k] + b1[k];
        }
    }
    __syncthreads();

    {
        int f  = tid & 63;
        int rg = tid >> 6;
        float acc[8];
        float bv = bn[f];
        #pragma unroll
        for (int t = 0; t < 8; t++) acc[t] = bv;
        #pragma unroll 8
        for (int k = 0; k < 64; k++) {
            float wv = Wns[f*65 + k];
            #pragma unroll
            for (int t = 0; t < 8; t++)
                acc[t] = fmaf(ns[(rg*8 + t)*68 + k], wv, acc[t]);
        }
        #pragma unroll
        for (int t = 0; t < 8; t++) {
            int r = rg*8 + t;
            g_h[(size_t)(row0 + r)*FF + f] = acc[t];
            hs[r*68 + f] = acc[t];
        }
    }
    __syncthreads();

    if (tid < 128) {
        int r = tid >> 2, hh = tid & 3;
        float sr = 0.f, sc = 0.f;
        #pragma unroll
        for (int x = 0; x < HD; x++) {
            float hv = hs[r*68 + hh*HD + x];
            sr = fmaf(hv, arow[x], sr);
            sc = fmaf(hv, acol[x], sc);
        }
        g_sr[(size_t)(row0 + r)*HH + hh] = sr;
        g_sc[(size_t)(row0 + r)*HH + hh] = sc;
    }
}

// ---------------- K2: edge pipeline, 4 positions/thread, LDS.128 weights -------
// 128 threads, 512 positions per block. Thread t owns positions t, t+128, t+256, t+384.
__global__ __launch_bounds__(128, 2) void k_edge(
    const float* __restrict__ edge, const int* __restrict__ adj,
    const float* __restrict__ g2, const float* __restrict__ b2,
    const float* __restrict__ We1, const float* __restrict__ be1,
    const float* __restrict__ We2, const float* __restrict__ be2,
    const float* __restrict__ lg, const float* __restrict__ lb,
    const float* __restrict__ A,
    float* __restrict__ e_out, float* __restrict__ adj_out) {

    // W1t[kk][k]: We1[kk][k]*g2[k], duplicated float2, contiguous in k
    // W2t[kk][o]: We2[o][kk],       duplicated float2, contiguous in o
    __shared__ __align__(16) float2 W1t[32*16], W2t[32*16];
    __shared__ float2 be1f[32], be2s[EE], lneg[EE], lneb[EE], aes[EE];

    int tid = threadIdx.x;
    for (int i = tid; i < 512; i += 128) {
        int k = i & 15;
        float w1 = We1[i] * g2[k];                 // i = kk*16 + k
        W1t[i] = make_float2(w1, w1);
        int kk2 = i >> 4, o2 = i & 15;
        float w2 = We2[o2*32 + kk2];
        W2t[i] = make_float2(w2, w2);
    }
    if (tid < 32) {
        float s = be1[tid];
        #pragma unroll
        for (int k = 0; k < 16; k++) s += b2[k] * We1[tid*16 + k];
        be1f[tid] = make_float2(s, s);
    }
    if (tid < EE) {
        lneg[tid] = make_float2(lg[tid], lg[tid]);
        lneb[tid] = make_float2(lb[tid], lb[tid]);
        be2s[tid] = make_float2(be2[tid], be2[tid]);
        float s = 0.f;
        #pragma unroll
        for (int h = 0; h < HH; h++) s += A[h*48 + 2*HD + tid];
        aes[tid] = make_float2(s, s);
    }

    // adj -> float (coalesced, independent)
    size_t base = (size_t)blockIdx.x * 512;
    {
        int4 av = ((const int4*)(adj + base))[tid];
        ((float4*)(adj_out + base))[tid] =
            make_float4((float)av.x, (float)av.y, (float)av.z, (float)av.w);
    }
    __syncthreads();

    const float4* e4 = (const float4*)edge;
    const float2 zero2 = make_float2(0.f, 0.f);
    const float2 neg1  = make_float2(-1.f, -1.f);
    const float2 inv16 = make_float2(1.f/16.f, 1.f/16.f);

    size_t pA = base + tid, pB = base + tid + 128;
    size_t pC = base + tid + 256, pD = base + tid + 384;

    float2 X0[EE], X1[EE];
    {
        float fa[EE], fb[EE], fc[EE], fd[EE];
        #pragma unroll
        for (int i = 0; i < 4; i++) {
            *(float4*)&fa[i*4] = e4[pA*4 + i];
            *(float4*)&fb[i*4] = e4[pB*4 + i];
            *(float4*)&fc[i*4] = e4[pC*4 + i];
            *(float4*)&fd[i*4] = e4[pD*4 + i];
        }
        #pragma unroll
        for (int k = 0; k < EE; k++) {
            X0[k] = make_float2(fa[k], fb[k]);
            X1[k] = make_float2(fc[k], fd[k]);
        }
    }

    // LN over E -> X = (x - mu) * rs  (gamma/beta folded into W1t/be1f)
    {
        float2 s0 = zero2, s1 = zero2;
        #pragma unroll
        for (int k = 0; k < EE; k++) { s0 = fadd2(s0, X0[k]); s1 = fadd2(s1, X1[k]); }
        float2 mu0 = fmul2(s0, inv16), mu1 = fmul2(s1, inv16);
        float2 q0 = zero2, q1 = zero2;
        #pragma unroll
        for (int k = 0; k < EE; k++) {
            float2 d0 = ffma2(mu0, neg1, X0[k]); q0 = ffma2(d0, d0, q0);
            float2 d1 = ffma2(mu1, neg1, X1[k]); q1 = ffma2(d1, d1, q1);
        }
        float2 v0 = fmul2(q0, inv16), v1 = fmul2(q1, inv16);
        float2 rs0 = make_float2(rsqrtf(v0.x + 1e-5f), rsqrtf(v0.y + 1e-5f));
        float2 rs1 = make_float2(rsqrtf(v1.x + 1e-5f), rsqrtf(v1.y + 1e-5f));
        #pragma unroll
        for (int k = 0; k < EE; k++) {
            X0[k] = fmul2(ffma2(mu0, neg1, X0[k]), rs0);
            X1[k] = fmul2(ffma2(mu1, neg1, X1[k]), rs1);
        }
    }

    // fused GEMM1 -> celu -> GEMM2; weights via LDS.128; 4 acc chains in GEMM1
    float2 Y0[EE], Y1[EE];
    #pragma unroll
    for (int o = 0; o < EE; o++) { Y0[o] = be2s[o]; Y1[o] = be2s[o]; }
    #pragma unroll 2
    for (int kk = 0; kk < 32; kk++) {
        const float4* w1p = (const float4*)&W1t[kk*16];
        float2 a0e = be1f[kk], a1e = a0e;
        float2 a0o = zero2,    a1o = zero2;
        #pragma unroll
        for (int q = 0; q < 8; q++) {
            float4 wv = w1p[q];
            float2 wA = make_float2(wv.x, wv.y);
            float2 wB = make_float2(wv.z, wv.w);
            a0e = ffma2(X0[2*q],   wA, a0e);
            a1e = ffma2(X1[2*q],   wA, a1e);
            a0o = ffma2(X0[2*q+1], wB, a0o);
            a1o = ffma2(X1[2*q+1], wB, a1o);
        }
        float2 h0 = celu2(fadd2(a0e, a0o));
        float2 h1 = celu2(fadd2(a1e, a1o));
        const float4* w2p = (const float4*)&W2t[kk*16];
        #pragma unroll
        for (int q = 0; q < 8; q++) {
            float4 wv = w2p[q];
            float2 wA = make_float2(wv.x, wv.y);
            float2 wB = make_float2(wv.z, wv.w);
            Y0[2*q]   = ffma2(h0, wA, Y0[2*q]);
            Y1[2*q]   = ffma2(h1, wA, Y1[2*q]);
            Y0[2*q+1] = ffma2(h0, wB, Y0[2*q+1]);
            Y1[2*q+1] = ffma2(h1, wB, Y1[2*q+1]);
        }
    }

    // residual (edge reload: L1-hot)
    {
        float fa[EE], fb[EE], fc[EE], fd[EE];
        #pragma unroll
        for (int i = 0; i < 4; i++) {
            *(float4*)&fa[i*4] = e4[pA*4 + i];
            *(float4*)&fb[i*4] = e4[pB*4 + i];
            *(float4*)&fc[i*4] = e4[pC*4 + i];
            *(float4*)&fd[i*4] = e4[pD*4 + i];
        }
        #pragma unroll
        for (int k = 0; k < EE; k++) {
            Y0[k] = fadd2(Y0[k], make_float2(fa[k], fb[k]));
            Y1[k] = fadd2(Y1[k], make_float2(fc[k], fd[k]));
        }
    }

    // final LN + se
    {
        float2 s0 = zero2, s1 = zero2;
        #pragma unroll
        for (int k = 0; k < EE; k++) { s0 = fadd2(s0, Y0[k]); s1 = fadd2(s1, Y1[k]); }
        float2 mu0 = fmul2(s0, inv16), mu1 = fmul2(s1, inv16);
        float2 q0 = zero2, q1 = zero2;
        #pragma unroll
        for (int k = 0; k < EE; k++) {
            float2 d0 = ffma2(mu0, neg1, Y0[k]); q0 = ffma2(d0, d0, q0);
            float2 d1 = ffma2(mu1, neg1, Y1[k]); q1 = ffma2(d1, d1, q1);
        }
        float2 v0 = fmul2(q0, inv16), v1 = fmul2(q1, inv16);
        float2 rs0 = make_float2(rsqrtf(v0.x + 1e-5f), rsqrtf(v0.y + 1e-5f));
        float2 rs1 = make_float2(rsqrtf(v1.x + 1e-5f), rsqrtf(v1.y + 1e-5f));
        float2 se0 = zero2, se1 = zero2;
        #pragma unroll
        for (int k = 0; k < EE; k++) {
            float2 d0 = ffma2(mu0, neg1, Y0[k]);
            float2 d1 = ffma2(mu1, neg1, Y1[k]);
            Y0[k] = ffma2(d0, fmul2(rs0, lneg[k]), lneb[k]);
            Y1[k] = ffma2(d1, fmul2(rs1, lneg[k]), lneb[k]);
            se0 = ffma2(Y0[k], aes[k], se0);
            se1 = ffma2(Y1[k], aes[k], se1);
        }
        g_se[pA] = se0.x; g_se[pB] = se0.y;
        g_se[pC] = se1.x; g_se[pD] = se1.y;
    }

    // stores (float4 per position)
    {
        float4* eo = (float4*)e_out;
        #pragma unroll
        for (int i = 0; i < 4; i++) {
            eo[pA*4 + i] = make_float4(Y0[i*4+0].x, Y0[i*4+1].x, Y0[i*4+2].x, Y0[i*4+3].x);
            eo[pB*4 + i] = make_float4(Y0[i*4+0].y, Y0[i*4+1].y, Y0[i*4+2].y, Y0[i*4+3].y);
            eo[pC*4 + i] = make_float4(Y1[i*4+0].x, Y1[i*4+1].x, Y1[i*4+2].x, Y1[i*4+3].x);
            eo[pD*4 + i] = make_float4(Y1[i*4+0].y, Y1[i*4+1].y, Y1[i*4+2].y, Y1[i*4+3].y);
        }
    }
}

// ---------------- K3: two-pass masked leaky softmax + aggregation --------------
__global__ __launch_bounds__(256) void k_attn(const int* __restrict__ adj) {
    __shared__ __align__(16) float hsm[128*64];
    __shared__ float scs[128*4];

    int tid = threadIdx.x;
    int sub = tid & 3;
    int hh  = (tid >> 2) & 3;
    int il  = tid >> 4;
    int b = blockIdx.y;
    int ig = blockIdx.x * 16 + il;
    int rowi = b*NN + ig;

    const float* sep = g_se + (size_t)rowi * NN;
    const int*   ap  = adj  + (size_t)rowi * NN;
    float sr_v = g_sr[rowi*HH + hh];
    const float* scg = g_sc + (size_t)b*NN*HH;

    float m = -3.4e38f;
    #pragma unroll 4
    for (int t = 0; t < 128; t++) {
        int j = sub + 4*t;
        float lgt = sr_v + scg[j*HH + hh] + sep[j];
        if (ap[j] == 0) lgt = -1e9f;
        lgt = lgt > 0.f ? lgt : 0.2f*lgt;
        lgt = fminf(fmaxf(lgt, -1e9f), 1e9f);
        m = fmaxf(m, lgt);
    }
    m = fmaxf(m, __shfl_xor_sync(0xffffffffu, m, 1));
    m = fmaxf(m, __shfl_xor_sync(0xffffffffu, m, 2));

    float ssum = 0.f;
    float a0 = 0.f, a1 = 0.f, a2 = 0.f, a3 = 0.f;
    for (int jt = 0; jt < 4; jt++) {
        int j0 = jt * 128;
        __syncthreads();
        {
            const float4* hsrc = (const float4*)(g_h + (size_t)(b*NN + j0) * FF);
            #pragma unroll
            for (int i = tid; i < 128*16; i += 256) ((float4*)hsm)[i] = hsrc[i];
            if (tid < 128)
                ((float4*)scs)[tid] = ((const float4*)(scg + (size_t)j0*HH))[tid];
        }
        __syncthreads();
        #pragma unroll 2
        for (int jl = 0; jl < 128; jl++) {
            int j = j0 + jl;
            float lgt = sr_v + scs[jl*4 + hh] + sep[j];
            if (ap[j] == 0) lgt = -1e9f;
            lgt = lgt > 0.f ? lgt : 0.2f*lgt;
            lgt = fminf(fmaxf(lgt, -1e9f), 1e9f);
            float w = __expf(lgt - m);
            ssum += w;
            float4 hv = *(const float4*)(hsm + jl*64 + hh*16 + sub*4);
            a0 = fmaf(w, hv.x, a0);
            a1 = fmaf(w, hv.y, a1);
            a2 = fmaf(w, hv.z, a2);
            a3 = fmaf(w, hv.w, a3);
        }
    }
    float inv = 1.f / ssum;
    *(float4*)(g_msg + (size_t)rowi*FF + hh*16 + sub*4) =
        make_float4(a0*inv, a1*inv, a2*inv, a3*inv);
}

// ---------------- K4: out proj + residual + leaky + LN (32 rows / block) -------
__global__ __launch_bounds__(256) void k_out(
        const float* __restrict__ node, const float* __restrict__ Wo,
        const float* __restrict__ bo, const float* __restrict__ lg,
        const float* __restrict__ lb, float* __restrict__ outp) {
    __shared__ __align__(16) float ms[32*68];
    __shared__ float Wos[64*65];
    __shared__ __align__(16) float hsr[32*68];

    int tid = threadIdx.x;
    int row0 = blockIdx.x * 32;

    {
        const float4* src = (const float4*)(g_msg + (size_t)row0 * FF);
        #pragma unroll
        for (int i = tid; i < 32*16; i += 256) {
            int r = i >> 4, c4 = i & 15;
            *(float4*)&ms[r*68 + c4*4] = src[i];
        }
    }
    #pragma unroll
    for (int i = tid; i < 64*64; i += 256) {
        int f = i >> 6, k = i & 63;
        Wos[f*65 + k] = Wo[i];
    }
    __syncthreads();

    {
        int f  = tid & 63;
        int rg = tid >> 6;
        float acc[8];
        float bv = bo[f];
        #pragma unroll
        for (int t = 0; t < 8; t++) acc[t] = bv;
        #pragma unroll 8
        for (int k = 0; k < 64; k++) {
            float wv = Wos[f*65 + k];
            #pragma unroll
            for (int t = 0; t < 8; t++)
                acc[t] = fmaf(ms[(rg*8 + t)*68 + k], wv, acc[t]);
        }
        #pragma unroll
        for (int t = 0; t < 8; t++) {
            int r = rg*8 + t;
            float v = acc[t] + node[(size_t)(row0 + r)*FF + f];
            v = v > 0.f ? v : 0.2f*v;
            hsr[r*68 + f] = v;
        }
    }
    __syncthreads();

    {
        int r = tid >> 3, sub = tid & 7;
        float s = 0.f;
        #pragma unroll
        for (int t = 0; t < 8; t++) s += hsr[r*68 + sub + 8*t];
        s += __shfl_xor_sync(0xffffffffu, s, 1);
        s += __shfl_xor_sync(0xffffffffu, s, 2);
        s += __shfl_xor_sync(0xffffffffu, s, 4);
        float mu = s * (1.f/FF);
        float q = 0.f;
        #pragma unroll
        for (int t = 0; t < 8; t++) { float d = hsr[r*68 + sub + 8*t] - mu; q += d*d; }
        q += __shfl_xor_sync(0xffffffffu, q, 1);
        q += __shfl_xor_sync(0xffffffffu, q, 2);
        q += __shfl_xor_sync(0xffffffffu, q, 4);
        float rsv = rsqrtf(q * (1.f/FF) + 1e-5f);
        #pragma unroll
        for (int t = 0; t < 8; t++) {
            int k = sub + 8*t;
            outp[(size_t)(row0 + r)*FF + k] = (hsr[r*68 + k] - mu) * rsv * lg[k] + lb[k];
        }
    }
}

// ---------------- launch -------------------------------------------------------
extern "C" void kernel_launch(void* const* d_in, const int* in_sizes, int n_in,
                              void* d_out, int out_size) {
    const float* node  = (const float*)d_in[0];
    const float* edge  = (const float*)d_in[1];
    const int*   adj   = (const int*)  d_in[2];
    const float* ln1_g = (const float*)d_in[3];
    const float* ln1_b = (const float*)d_in[4];
    const float* Wn    = (const float*)d_in[5];
    const float* bn    = (const float*)d_in[6];
    const float* ln2_g = (const float*)d_in[7];
    const float* ln2_b = (const float*)d_in[8];
    const float* We1   = (const float*)d_in[9];
    const float* be1   = (const float*)d_in[10];
    const float* We2   = (const float*)d_in[11];
    const float* be2   = (const float*)d_in[12];
    const float* lne_g = (const float*)d_in[13];
    const float* lne_b = (const float*)d_in[14];
    const float* attnA = (const float*)d_in[15];
    const float* Wo    = (const float*)d_in[16];
    const float* bo    = (const float*)d_in[17];
    const float* lno_g = (const float*)d_in[18];
    const float* lno_b = (const float*)d_in[19];

    float* out     = (float*)d_out;
    float* e_out   = out + (size_t)ROWS * FF;
    float* adj_out = e_out + (size_t)NPOS * EE;

    k_node<<<ROWS/32, 256>>>(node, ln1_g, ln1_b, Wn, bn, attnA);
    k_edge<<<NPOS/512, 128>>>(edge, adj, ln2_g, ln2_b, We1, be1, We2, be2,
                              lne_g, lne_b, attnA, e_out, adj_out);
    k_attn<<<dim3(NN/16, BB), 256>>>(adj);
    k_out<<<ROWS/32, 256>>>(node, Wo, bo, lno_g, lno_b, out);
}